// round 1
// baseline (speedup 1.0000x reference)
#include <cuda_runtime.h>

typedef unsigned long long u64;

#define Bn 256
#define Tn 256
#define Sn 20
#define NROWS (Bn*Tn)   // 65536

// scratch: zx[row][96] = h_inner[row] @ Wo + bo   (outer-LSTM input preactivations)
__device__ float g_zx[NROWS * 96];

// ---------- packed f32x2 helpers ----------
__device__ __forceinline__ u64 ffma2(u64 a, u64 b, u64 c){
    u64 d;
    asm("fma.rn.f32x2 %0, %1, %2, %3;" : "=l"(d) : "l"(a), "l"(b), "l"(c));
    return d;
}
__device__ __forceinline__ u64 pk2(float lo, float hi){
    u64 r; asm("mov.b64 %0, {%1, %2};" : "=l"(r) : "f"(lo), "f"(hi)); return r;
}
__device__ __forceinline__ void up2(u64 v, float& lo, float& hi){
    asm("mov.b64 {%0, %1}, %2;" : "=f"(lo), "=f"(hi) : "l"(v));
}

// ---------- activations (fp32, safe at extremes) ----------
__device__ __forceinline__ float sigf(float x){
    // exp overflow -> inf -> 1/(1+inf)=0 (correct limit); underflow -> 0 -> 1 (correct)
    return __fdividef(1.0f, 1.0f + __expf(-x));
}
__device__ __forceinline__ float tanh_f(float x){
    x = fminf(fmaxf(x, -15.0f), 15.0f);   // avoid inf/inf
    float e = __expf(2.0f * x);
    return __fdividef(e - 1.0f, e + 1.0f);
}

// =====================================================================
// Inner LSTM: 65536 rows, S=20, U1=32, D=1. Thread owns 2 rows (f32x2).
// h state in per-thread SMEM columns (double buffered), c in registers.
// Epilogue: zx = h_final @ Wo + bo  (removes non-recurrent GEMM from outer).
// =====================================================================
__global__ void __launch_bounds__(128) inner_kernel(
    const float* __restrict__ x,  const float* __restrict__ Wi,
    const float* __restrict__ Ui, const float* __restrict__ bi,
    const float* __restrict__ Wo, const float* __restrict__ bo)
{
    extern __shared__ char smem[];
    float* wuf = (float*)smem;            // dup Ui: [k][u][g][2]  -> 8192 floats (32 KB)
    float* wif = wuf + 8192;              // dup Wi: [u][g][2]     -> 256 floats
    float* bif = wif + 256;               // dup bi: [u][g][2]     -> 256 floats
    u64*  hsm  = (u64*)(smem + 32768 + 1024 + 1024); // [2][32][128] -> 64 KB

    const int tid = threadIdx.x;

    // cooperative load + duplicate weights (gate order i,f,g,o: col = g*32+u)
    for (int idx = tid; idx < 4096; idx += 128){
        int k = idx >> 7, col = idx & 127;
        int g = col >> 5,  u  = col & 31;
        float w = Ui[idx];
        int o = (((k << 5) + u) * 4 + g) * 2;
        wuf[o] = w; wuf[o + 1] = w;
    }
    {
        int col = tid;
        int g = col >> 5, u = col & 31;
        int o = (u * 4 + g) * 2;
        float w = Wi[col]; wif[o] = w; wif[o + 1] = w;
        float b = bi[col]; bif[o] = b; bif[o + 1] = b;
    }
    __syncthreads();

    const ulonglong2* wu2 = (const ulonglong2*)wuf;
    const ulonglong2* wi2 = (const ulonglong2*)wif;
    const ulonglong2* bi2 = (const ulonglong2*)bif;

    const int  gtid = blockIdx.x * 128 + tid;
    const long r0 = 2L * gtid, r1 = r0 + 1;
    const float* x0p = x + r0 * Sn;
    const float* x1p = x + r1 * Sn;

    float cA[32], cB[32];
    #pragma unroll
    for (int u = 0; u < 32; u++){ cA[u] = 0.f; cB[u] = 0.f; }
    #pragma unroll
    for (int k = 0; k < 32; k++) hsm[(k << 7) + tid] = 0ULL;  // h0 = 0 (buf 0)

    float xn0 = x0p[0], xn1 = x1p[0];

    for (int s = 0; s < Sn; s++){
        u64 xv = pk2(xn0, xn1);
        if (s + 1 < Sn){ xn0 = x0p[s + 1]; xn1 = x1p[s + 1]; }  // prefetch next x
        const u64* hb = hsm + ((s & 1) << 12);        // read buffer
        u64*       hw = hsm + (((s + 1) & 1) << 12);  // write buffer

        #pragma unroll
        for (int ut = 0; ut < 4; ut++){
            u64 a[8][4];
            #pragma unroll
            for (int u8 = 0; u8 < 8; u8++){
                int u = (ut << 3) + u8;
                ulonglong2 wA = wi2[u * 2], wB = wi2[u * 2 + 1];
                ulonglong2 bA = bi2[u * 2], bB = bi2[u * 2 + 1];
                a[u8][0] = ffma2(xv, wA.x, bA.x);
                a[u8][1] = ffma2(xv, wA.y, bA.y);
                a[u8][2] = ffma2(xv, wB.x, bB.x);
                a[u8][3] = ffma2(xv, wB.y, bB.y);
            }
            #pragma unroll 4
            for (int k = 0; k < 32; k++){
                u64 hk = hb[(k << 7) + tid];
                #pragma unroll
                for (int u8 = 0; u8 < 8; u8++){
                    int wo_ = ((k << 5) + (ut << 3) + u8) << 1;
                    ulonglong2 w01 = wu2[wo_], w23 = wu2[wo_ + 1];
                    a[u8][0] = ffma2(hk, w01.x, a[u8][0]);
                    a[u8][1] = ffma2(hk, w01.y, a[u8][1]);
                    a[u8][2] = ffma2(hk, w23.x, a[u8][2]);
                    a[u8][3] = ffma2(hk, w23.y, a[u8][3]);
                }
            }
            #pragma unroll
            for (int u8 = 0; u8 < 8; u8++){
                int u = (ut << 3) + u8;
                float zi0, zi1, zf0, zf1, zg0, zg1, zo0, zo1;
                up2(a[u8][0], zi0, zi1);
                up2(a[u8][1], zf0, zf1);
                up2(a[u8][2], zg0, zg1);
                up2(a[u8][3], zo0, zo1);
                float i0 = sigf(zi0),   i1 = sigf(zi1);
                float f0 = sigf(zf0),   f1 = sigf(zf1);
                float g0 = tanh_f(zg0), g1 = tanh_f(zg1);
                float o0 = sigf(zo0),   o1 = sigf(zo1);
                float c0 = f0 * cA[u] + i0 * g0;
                float c1 = f1 * cB[u] + i1 * g1;
                cA[u] = c0; cB[u] = c1;
                hw[(u << 7) + tid] = pk2(o0 * tanh_f(c0), o1 * tanh_f(c1));
            }
        }
    }

    // epilogue: zx = h_final @ Wo + bo (h_final is in buffer 0 since S=20 even)
    const u64* hf = hsm;
    float* z0p = g_zx + r0 * 96;
    float* z1p = g_zx + r1 * 96;
    #pragma unroll 1
    for (int c4 = 0; c4 < 24; c4++){
        float4 b4 = __ldg((const float4*)(bo + c4 * 4));
        u64 ac0 = pk2(b4.x, b4.x), ac1 = pk2(b4.y, b4.y);
        u64 ac2 = pk2(b4.z, b4.z), ac3 = pk2(b4.w, b4.w);
        #pragma unroll 4
        for (int k = 0; k < 32; k++){
            u64 hk = hf[(k << 7) + tid];
            float4 w4 = __ldg((const float4*)(Wo + k * 96 + c4 * 4));
            ac0 = ffma2(hk, pk2(w4.x, w4.x), ac0);
            ac1 = ffma2(hk, pk2(w4.y, w4.y), ac1);
            ac2 = ffma2(hk, pk2(w4.z, w4.z), ac2);
            ac3 = ffma2(hk, pk2(w4.w, w4.w), ac3);
        }
        float a0l,a0h,a1l,a1h,a2l,a2h,a3l,a3h;
        up2(ac0,a0l,a0h); up2(ac1,a1l,a1h); up2(ac2,a2l,a2h); up2(ac3,a3l,a3h);
        *(float4*)(z0p + c4 * 4) = make_float4(a0l, a1l, a2l, a3l);
        *(float4*)(z1p + c4 * 4) = make_float4(a0h, a1h, a2h, a3h);
    }
}

// =====================================================================
// Outer LSTM + dense head: one warp per batch row (uniform length -> no
// intra-warp divergence across steps). Only the recurrent 24x96 GEMV is
// on the serial path; zx rows are prefetched one step ahead.
// =====================================================================
__global__ void __launch_bounds__(256) outer_kernel(
    const int*   __restrict__ lengths,
    const float* __restrict__ Uo,
    const float* __restrict__ Wd,
    const float* __restrict__ bd,
    float*       __restrict__ out)
{
    __shared__ float Uo_s[24 * 96];
    __shared__ float Wd_s[24];
    __shared__ float h_sm[8][25];

    const int tid = threadIdx.x;
    for (int i = tid; i < 24 * 96; i += 256) Uo_s[i] = Uo[i];
    if (tid < 24) Wd_s[tid] = Wd[tid];
    __syncthreads();

    const int w = tid >> 5, l = tid & 31;
    const int b = blockIdx.x * 8 + w;
    const int len = lengths[b];                 // in [1, T]
    const float* zr = g_zx + (size_t)b * Tn * 96;

    float h = 0.f, c = 0.f;
    if (l < 24) h_sm[w][l] = 0.f;
    __syncwarp();

    float zn0 = 0.f, zn1 = 0.f, zn2 = 0.f, zn3 = 0.f;
    if (l < 24){
        zn0 = zr[l]; zn1 = zr[24 + l]; zn2 = zr[48 + l]; zn3 = zr[72 + l];
    }

    for (int t = 0; t < len; t++){
        float z0 = zn0, z1 = zn1, z2 = zn2, z3 = zn3;
        if (l < 24){
            if (t + 1 < len){
                const float* zq = zr + (size_t)(t + 1) * 96;
                zn0 = zq[l]; zn1 = zq[24 + l]; zn2 = zq[48 + l]; zn3 = zq[72 + l];
            }
            #pragma unroll
            for (int k = 0; k < 24; k++){
                float hk = h_sm[w][k];
                z0 = fmaf(hk, Uo_s[k * 96 + l],      z0);
                z1 = fmaf(hk, Uo_s[k * 96 + 24 + l], z1);
                z2 = fmaf(hk, Uo_s[k * 96 + 48 + l], z2);
                z3 = fmaf(hk, Uo_s[k * 96 + 72 + l], z3);
            }
            float fi = sigf(z0), ff = sigf(z1), fg = tanh_f(z2), fo = sigf(z3);
            c = ff * c + fi * fg;
            h = fo * tanh_f(c);
        }
        __syncwarp();
        if (l < 24) h_sm[w][l] = h;
        __syncwarp();
    }

    // dense sigmoid head: out[b] = sigmoid(h . Wd + bd)
    float p = (l < 24) ? h * Wd_s[l] : 0.f;
    #pragma unroll
    for (int off = 16; off; off >>= 1) p += __shfl_xor_sync(0xffffffffu, p, off);
    if (l == 0) out[b] = sigf(p + bd[0]);
}

extern "C" void kernel_launch(void* const* d_in, const int* in_sizes, int n_in,
                              void* d_out, int out_size)
{
    const float* x       = (const float*)d_in[0];
    const int*   lengths = (const int*)  d_in[1];
    const float* Wi      = (const float*)d_in[2];
    const float* Ui      = (const float*)d_in[3];
    const float* bi      = (const float*)d_in[4];
    const float* Wo      = (const float*)d_in[5];
    const float* Uo      = (const float*)d_in[6];
    const float* bo      = (const float*)d_in[7];
    const float* Wd      = (const float*)d_in[8];
    const float* bd      = (const float*)d_in[9];
    float* out = (float*)d_out;

    const int smem_bytes = 32768 + 1024 + 1024 + 65536;  // 100352
    cudaFuncSetAttribute(inner_kernel,
                         cudaFuncAttributeMaxDynamicSharedMemorySize, smem_bytes);

    inner_kernel<<<256, 128, smem_bytes>>>(x, Wi, Ui, bi, Wo, bo);
    outer_kernel<<<32, 256>>>(lengths, Uo, Wd, bd, out);
}

// round 2
// speedup vs baseline: 1.5844x; 1.5844x over previous
#include <cuda_runtime.h>

typedef unsigned long long u64;

#define Bn 256
#define Tn 256
#define Sn 20
#define NROWS (Bn*Tn)   // 65536

// scratch: zx[row][96] = h_inner[row] @ Wo + bo   (outer-LSTM input preactivations)
__device__ float g_zx[NROWS * 96];

// ---------- packed f32x2 helpers ----------
__device__ __forceinline__ u64 ffma2(u64 a, u64 b, u64 c){
    u64 d;
    asm("fma.rn.f32x2 %0, %1, %2, %3;" : "=l"(d) : "l"(a), "l"(b), "l"(c));
    return d;
}
__device__ __forceinline__ u64 pk2(float lo, float hi){
    u64 r; asm("mov.b64 %0, {%1, %2};" : "=l"(r) : "f"(lo), "f"(hi)); return r;
}
__device__ __forceinline__ void up2(u64 v, float& lo, float& hi){
    asm("mov.b64 {%0, %1}, %2;" : "=f"(lo), "=f"(hi) : "l"(v));
}

// ---------- activations (fp32, safe at extremes) ----------
__device__ __forceinline__ float sigf(float x){
    return __fdividef(1.0f, 1.0f + __expf(-x));
}
__device__ __forceinline__ float tanh_f(float x){
    x = fminf(fmaxf(x, -15.0f), 15.0f);
    float e = __expf(2.0f * x);
    return __fdividef(e - 1.0f, e + 1.0f);
}

// =====================================================================
// Inner LSTM: 65536 rows, S=20, U1=32, D=1.
// Block = 256 threads = 64 row-pair columns x 4 unit-groups (8 units each).
// Thread owns 2 rows (f32x2) x 8 units: a[8][4]=64 regs, c=16 regs -> no spill,
// 2 blocks/SM = 4 warps/SMSP for latency hiding. h double-buffered in SMEM,
// one __syncthreads per step. Epilogue folds zx = h @ Wo + bo.
// =====================================================================
__global__ void __launch_bounds__(256, 2) inner_kernel(
    const float* __restrict__ x,  const float* __restrict__ Wi,
    const float* __restrict__ Ui, const float* __restrict__ bi,
    const float* __restrict__ Wo, const float* __restrict__ bo)
{
    extern __shared__ char smem[];
    float* wuf = (float*)smem;            // dup Ui [k][u][g][2]: 8192 f (32KB)
    float* wif = wuf + 8192;              // dup Wi [u][g][2]: 256 f
    float* bif = wif + 256;               // dup bi [u][g][2]: 256 f
    float* xsm = bif + 256;               // x stage [128 rows][20]: 2560 f (10KB)
    u64*  hsm  = (u64*)(xsm + 2560);      // h [2][32][64 cols]: 4096 u64 (32KB)

    const int tid = threadIdx.x;
    const int col = tid & 63;             // row-pair column
    const int ug  = tid >> 6;             // unit group 0..3
    const int ubase = ug * 8;

    // cooperative load + duplicate weights (gate order i,f,g,o: Ui col = g*32+u)
    for (int idx = tid; idx < 4096; idx += 256){
        int k = idx >> 7, cw = idx & 127;
        int g = cw >> 5,  u  = cw & 31;
        float w = Ui[idx];
        int o = (((k << 5) + u) * 4 + g) * 2;
        wuf[o] = w; wuf[o + 1] = w;
    }
    if (tid < 128){
        int g = tid >> 5, u = tid & 31;
        int o = (u * 4 + g) * 2;
        float w = Wi[tid]; wif[o] = w; wif[o + 1] = w;
        float b = bi[tid]; bif[o] = b; bif[o + 1] = b;
    }
    // stage x for this block's 128 rows (contiguous, coalesced)
    {
        const float* xg = x + (size_t)blockIdx.x * 128 * Sn;
        for (int idx = tid; idx < 128 * Sn; idx += 256) xsm[idx] = xg[idx];
    }
    // h0 = 0 in buffer 0
    for (int i = tid; i < 2048; i += 256) hsm[i] = 0ULL;
    __syncthreads();

    const ulonglong2* wu2 = (const ulonglong2*)wuf;
    const ulonglong2* wi2 = (const ulonglong2*)wif;
    const ulonglong2* bi2 = (const ulonglong2*)bif;

    float cA[8], cB[8];
    #pragma unroll
    for (int u8 = 0; u8 < 8; u8++){ cA[u8] = 0.f; cB[u8] = 0.f; }

    const float* x0s = xsm + (2 * col) * Sn;
    const float* x1s = xsm + (2 * col + 1) * Sn;

    #pragma unroll 1
    for (int s = 0; s < Sn; s++){
        u64 xv = pk2(x0s[s], x1s[s]);
        const u64* hb = hsm + ((s & 1) << 11);        // read buffer
        u64*       hw = hsm + (((s + 1) & 1) << 11);  // write buffer

        u64 a[8][4];
        #pragma unroll
        for (int u8 = 0; u8 < 8; u8++){
            int u = ubase + u8;
            ulonglong2 wA = wi2[u * 2], wB = wi2[u * 2 + 1];
            ulonglong2 bA = bi2[u * 2], bB = bi2[u * 2 + 1];
            a[u8][0] = ffma2(xv, wA.x, bA.x);
            a[u8][1] = ffma2(xv, wA.y, bA.y);
            a[u8][2] = ffma2(xv, wB.x, bB.x);
            a[u8][3] = ffma2(xv, wB.y, bB.y);
        }
        #pragma unroll 4
        for (int k = 0; k < 32; k++){
            u64 hk = hb[(k << 6) + col];
            #pragma unroll
            for (int u8 = 0; u8 < 8; u8++){
                int wo_ = ((k << 5) + ubase + u8) << 1;
                ulonglong2 w01 = wu2[wo_], w23 = wu2[wo_ + 1];
                a[u8][0] = ffma2(hk, w01.x, a[u8][0]);
                a[u8][1] = ffma2(hk, w01.y, a[u8][1]);
                a[u8][2] = ffma2(hk, w23.x, a[u8][2]);
                a[u8][3] = ffma2(hk, w23.y, a[u8][3]);
            }
        }
        #pragma unroll
        for (int u8 = 0; u8 < 8; u8++){
            float zi0, zi1, zf0, zf1, zg0, zg1, zo0, zo1;
            up2(a[u8][0], zi0, zi1);
            up2(a[u8][1], zf0, zf1);
            up2(a[u8][2], zg0, zg1);
            up2(a[u8][3], zo0, zo1);
            float i0 = sigf(zi0),   i1 = sigf(zi1);
            float f0 = sigf(zf0),   f1 = sigf(zf1);
            float g0 = tanh_f(zg0), g1 = tanh_f(zg1);
            float o0 = sigf(zo0),   o1 = sigf(zo1);
            float c0 = f0 * cA[u8] + i0 * g0;
            float c1 = f1 * cB[u8] + i1 * g1;
            cA[u8] = c0; cB[u8] = c1;
            hw[((ubase + u8) << 6) + col] = pk2(o0 * tanh_f(c0), o1 * tanh_f(c1));
        }
        __syncthreads();
    }

    // epilogue: zx = h_final @ Wo + bo; final h is in buffer 0 (Sn even).
    // unit-group ug computes 24 of the 96 output columns.
    const u64* hf = hsm;
    const long pair = (long)blockIdx.x * 64 + col;
    const long r0 = 2 * pair, r1 = r0 + 1;
    float* z0p = g_zx + r0 * 96 + ug * 24;
    float* z1p = g_zx + r1 * 96 + ug * 24;
    #pragma unroll 1
    for (int c4 = 0; c4 < 6; c4++){
        float4 b4 = __ldg((const float4*)(bo + ug * 24 + c4 * 4));
        u64 ac0 = pk2(b4.x, b4.x), ac1 = pk2(b4.y, b4.y);
        u64 ac2 = pk2(b4.z, b4.z), ac3 = pk2(b4.w, b4.w);
        #pragma unroll 4
        for (int k = 0; k < 32; k++){
            u64 hk = hf[(k << 6) + col];
            float4 w4 = __ldg((const float4*)(Wo + k * 96 + ug * 24 + c4 * 4));
            ac0 = ffma2(hk, pk2(w4.x, w4.x), ac0);
            ac1 = ffma2(hk, pk2(w4.y, w4.y), ac1);
            ac2 = ffma2(hk, pk2(w4.z, w4.z), ac2);
            ac3 = ffma2(hk, pk2(w4.w, w4.w), ac3);
        }
        float a0l,a0h,a1l,a1h,a2l,a2h,a3l,a3h;
        up2(ac0,a0l,a0h); up2(ac1,a1l,a1h); up2(ac2,a2l,a2h); up2(ac3,a3l,a3h);
        *(float4*)(z0p + c4 * 4) = make_float4(a0l, a1l, a2l, a3l);
        *(float4*)(z1p + c4 * 4) = make_float4(a0h, a1h, a2h, a3h);
    }
}

// =====================================================================
// Outer LSTM + dense head: one WARP per batch row, 256 blocks (fills SMs,
// short lengths retire early). h broadcast via shfl (no SMEM round-trip).
// =====================================================================
__global__ void __launch_bounds__(32) outer_kernel(
    const int*   __restrict__ lengths,
    const float* __restrict__ Uo,
    const float* __restrict__ Wd,
    const float* __restrict__ bd,
    float*       __restrict__ out)
{
    __shared__ float Uo_s[24 * 96 + 32];   // padded so l<32 reads stay in-bounds

    const int l = threadIdx.x;
    const int b = blockIdx.x;

    for (int i = l; i < 24 * 96 + 32; i += 32)
        Uo_s[i] = (i < 24 * 96) ? Uo[i] : 0.f;
    __syncwarp();

    const int len = lengths[b];            // in [1, T]
    const float* zr = g_zx + (size_t)b * Tn * 96;
    const bool act = (l < 24);

    float h = 0.f, c = 0.f;
    float zn0 = 0.f, zn1 = 0.f, zn2 = 0.f, zn3 = 0.f;
    if (act){
        zn0 = zr[l]; zn1 = zr[24 + l]; zn2 = zr[48 + l]; zn3 = zr[72 + l];
    }

    for (int t = 0; t < len; t++){
        float z0 = zn0, z1 = zn1, z2 = zn2, z3 = zn3;
        if (act && t + 1 < len){
            const float* zq = zr + (size_t)(t + 1) * 96;
            zn0 = zq[l]; zn1 = zq[24 + l]; zn2 = zq[48 + l]; zn3 = zq[72 + l];
        }
        #pragma unroll
        for (int k = 0; k < 24; k++){
            float hk = __shfl_sync(0xffffffffu, h, k);
            z0 = fmaf(hk, Uo_s[k * 96 + l],      z0);
            z1 = fmaf(hk, Uo_s[k * 96 + 24 + l], z1);
            z2 = fmaf(hk, Uo_s[k * 96 + 48 + l], z2);
            z3 = fmaf(hk, Uo_s[k * 96 + 72 + l], z3);
        }
        float fi = sigf(z0), ff = sigf(z1), fg = tanh_f(z2), fo = sigf(z3);
        c = ff * c + fi * fg;
        h = fo * tanh_f(c);
        // lanes >= 24 compute bounded garbage (z finite), never read back
    }

    // dense sigmoid head: out[b] = sigmoid(h . Wd + bd)
    float p = act ? h * Wd[l] : 0.f;
    #pragma unroll
    for (int off = 16; off; off >>= 1) p += __shfl_xor_sync(0xffffffffu, p, off);
    if (l == 0) out[b] = sigf(p + bd[0]);
}

extern "C" void kernel_launch(void* const* d_in, const int* in_sizes, int n_in,
                              void* d_out, int out_size)
{
    const float* x       = (const float*)d_in[0];
    const int*   lengths = (const int*)  d_in[1];
    const float* Wi      = (const float*)d_in[2];
    const float* Ui      = (const float*)d_in[3];
    const float* bi      = (const float*)d_in[4];
    const float* Wo      = (const float*)d_in[5];
    const float* Uo      = (const float*)d_in[6];
    const float* bo      = (const float*)d_in[7];
    const float* Wd      = (const float*)d_in[8];
    const float* bd      = (const float*)d_in[9];
    float* out = (float*)d_out;

    // smem: 32768 (wuf) + 1024 (wif) + 1024 (bif) + 10240 (xsm) + 32768 (hsm)
    const int smem_bytes = 32768 + 1024 + 1024 + 10240 + 32768;  // 77824
    cudaFuncSetAttribute(inner_kernel,
                         cudaFuncAttributeMaxDynamicSharedMemorySize, smem_bytes);

    inner_kernel<<<512, 256, smem_bytes>>>(x, Wi, Ui, bi, Wo, bo);
    outer_kernel<<<256, 32>>>(lengths, Uo, Wd, bd, out);
}

// round 3
// speedup vs baseline: 1.9662x; 1.2410x over previous
#include <cuda_runtime.h>

typedef unsigned long long u64;

#define Bn 256
#define Tn 256
#define Sn 20
#define NROWS (Bn*Tn)   // 65536

__device__ float g_zx[NROWS * 96];   // zx[row][96] = h_inner[row] @ Wo + bo

// ---------- packed f32x2 helpers ----------
__device__ __forceinline__ u64 ffma2(u64 a, u64 b, u64 c){
    u64 d;
    asm("fma.rn.f32x2 %0, %1, %2, %3;" : "=l"(d) : "l"(a), "l"(b), "l"(c));
    return d;
}
__device__ __forceinline__ u64 pk2(float lo, float hi){
    u64 r; asm("mov.b64 %0, {%1, %2};" : "=l"(r) : "f"(lo), "f"(hi)); return r;
}
__device__ __forceinline__ void up2(u64 v, float& lo, float& hi){
    asm("mov.b64 {%0, %1}, %2;" : "=f"(lo), "=f"(hi) : "l"(v));
}

// ---------- slim activations (exact limits, no clamps, no NaN) ----------
__device__ __forceinline__ float ex2f(float x){
    float r; asm("ex2.approx.ftz.f32 %0, %1;" : "=f"(r) : "f"(x)); return r;
}
__device__ __forceinline__ float rcpf(float x){
    float r; asm("rcp.approx.ftz.f32 %0, %1;" : "=f"(r) : "f"(x)); return r;
}
__device__ __forceinline__ float sigf(float x){
    // 1/(1+2^(-x*log2e)); x->+inf: ex2->0 -> 1; x->-inf: ex2->inf -> rcp->0
    return rcpf(1.0f + ex2f(-1.4426950408889634f * x));
}
__device__ __forceinline__ float tanh_f(float x){
    // 1 - 2/(2^(2x*log2e)+1); +inf -> 1, -inf -> -1, never NaN
    return fmaf(-2.0f, rcpf(1.0f + ex2f(2.8853900817779268f * x)), 1.0f);
}

// =====================================================================
// Inner LSTM: 65536 rows, S=20, U1=32, D=1.
// Block = 256 threads = 32 row-pair columns x 8 unit-groups (4 units each).
// a[4][4]=32 regs + c=8 regs -> ~70 regs, 3 blocks/SM = 6 warps/SMSP.
// h double-buffered in SMEM. Epilogue folds zx = h @ Wo + bo.
// =====================================================================
__global__ void __launch_bounds__(256, 3) inner_kernel(
    const float* __restrict__ x,  const float* __restrict__ Wi,
    const float* __restrict__ Ui, const float* __restrict__ bi,
    const float* __restrict__ Wo, const float* __restrict__ bo)
{
    extern __shared__ char smem[];
    float* wuf = (float*)smem;            // dup Ui [k][u][g][2]: 8192 f (32KB)
    float* wif = wuf + 8192;              // dup Wi [u][g][2]: 256 f
    float* bif = wif + 256;               // dup bi [u][g][2]: 256 f
    float* xsm = bif + 256;               // x stage [64 rows][20]: 1280 f
    u64*  hsm  = (u64*)(xsm + 1280);      // h [2][32 u][32 col]: 2048 u64 (16KB)

    const int tid = threadIdx.x;
    const int col = tid & 31;             // row-pair column (warp-lane)
    const int ug  = tid >> 5;             // unit group 0..7 (= warp id)
    const int ubase = ug * 4;

    // cooperative load + duplicate weights (gate order i,f,g,o: Ui col = g*32+u)
    for (int idx = tid; idx < 4096; idx += 256){
        int k = idx >> 7, cw = idx & 127;
        int g = cw >> 5,  u  = cw & 31;
        float w = Ui[idx];
        int o = (((k << 5) + u) * 4 + g) * 2;
        wuf[o] = w; wuf[o + 1] = w;
    }
    if (tid < 128){
        int g = tid >> 5, u = tid & 31;
        int o = (u * 4 + g) * 2;
        float w = Wi[tid]; wif[o] = w; wif[o + 1] = w;
        float b = bi[tid]; bif[o] = b; bif[o + 1] = b;
    }
    {   // stage x for this block's 64 rows
        const float* xg = x + (size_t)blockIdx.x * 64 * Sn;
        for (int idx = tid; idx < 64 * Sn; idx += 256) xsm[idx] = xg[idx];
    }
    for (int i = tid; i < 1024; i += 256) hsm[i] = 0ULL;  // h0 = 0 (buf 0)
    __syncthreads();

    const ulonglong2* wu2 = (const ulonglong2*)wuf;
    const ulonglong2* wi2 = (const ulonglong2*)wif;
    const ulonglong2* bi2 = (const ulonglong2*)bif;

    float cA[4], cB[4];
    #pragma unroll
    for (int u8 = 0; u8 < 4; u8++){ cA[u8] = 0.f; cB[u8] = 0.f; }

    const float* x0s = xsm + (2 * col) * Sn;
    const float* x1s = xsm + (2 * col + 1) * Sn;

    #pragma unroll 1
    for (int s = 0; s < Sn; s++){
        u64 xv = pk2(x0s[s], x1s[s]);
        const u64* hb = hsm + ((s & 1) << 10);
        u64*       hw = hsm + (((s + 1) & 1) << 10);

        u64 a[4][4];
        #pragma unroll
        for (int u8 = 0; u8 < 4; u8++){
            int u = ubase + u8;
            ulonglong2 wA = wi2[u * 2], wB = wi2[u * 2 + 1];
            ulonglong2 bA = bi2[u * 2], bB = bi2[u * 2 + 1];
            a[u8][0] = ffma2(xv, wA.x, bA.x);
            a[u8][1] = ffma2(xv, wA.y, bA.y);
            a[u8][2] = ffma2(xv, wB.x, bB.x);
            a[u8][3] = ffma2(xv, wB.y, bB.y);
        }
        #pragma unroll 8
        for (int k = 0; k < 32; k++){
            u64 hk = hb[(k << 5) + col];
            #pragma unroll
            for (int u8 = 0; u8 < 4; u8++){
                int wo_ = ((k << 5) + ubase + u8) << 1;
                ulonglong2 w01 = wu2[wo_], w23 = wu2[wo_ + 1];
                a[u8][0] = ffma2(hk, w01.x, a[u8][0]);
                a[u8][1] = ffma2(hk, w01.y, a[u8][1]);
                a[u8][2] = ffma2(hk, w23.x, a[u8][2]);
                a[u8][3] = ffma2(hk, w23.y, a[u8][3]);
            }
        }
        #pragma unroll
        for (int u8 = 0; u8 < 4; u8++){
            float zi0, zi1, zf0, zf1, zg0, zg1, zo0, zo1;
            up2(a[u8][0], zi0, zi1);
            up2(a[u8][1], zf0, zf1);
            up2(a[u8][2], zg0, zg1);
            up2(a[u8][3], zo0, zo1);
            float i0 = sigf(zi0),   i1 = sigf(zi1);
            float f0 = sigf(zf0),   f1 = sigf(zf1);
            float g0 = tanh_f(zg0), g1 = tanh_f(zg1);
            float o0 = sigf(zo0),   o1 = sigf(zo1);
            float c0 = f0 * cA[u8] + i0 * g0;
            float c1 = f1 * cB[u8] + i1 * g1;
            cA[u8] = c0; cB[u8] = c1;
            hw[((ubase + u8) << 5) + col] = pk2(o0 * tanh_f(c0), o1 * tanh_f(c1));
        }
        __syncthreads();
    }

    // epilogue: zx = h_final @ Wo + bo (final h in buffer 0, Sn even).
    // unit-group ug computes 12 of the 96 output columns.
    const u64* hf = hsm;
    const long pair = (long)blockIdx.x * 32 + col;
    const long r0 = 2 * pair, r1 = r0 + 1;
    float* z0p = g_zx + r0 * 96 + ug * 12;
    float* z1p = g_zx + r1 * 96 + ug * 12;
    #pragma unroll 1
    for (int c4 = 0; c4 < 3; c4++){
        float4 b4 = __ldg((const float4*)(bo + ug * 12 + c4 * 4));
        u64 ac0 = pk2(b4.x, b4.x), ac1 = pk2(b4.y, b4.y);
        u64 ac2 = pk2(b4.z, b4.z), ac3 = pk2(b4.w, b4.w);
        #pragma unroll 4
        for (int k = 0; k < 32; k++){
            u64 hk = hf[(k << 5) + col];
            float4 w4 = __ldg((const float4*)(Wo + k * 96 + ug * 12 + c4 * 4));
            ac0 = ffma2(hk, pk2(w4.x, w4.x), ac0);
            ac1 = ffma2(hk, pk2(w4.y, w4.y), ac1);
            ac2 = ffma2(hk, pk2(w4.z, w4.z), ac2);
            ac3 = ffma2(hk, pk2(w4.w, w4.w), ac3);
        }
        float a0l,a0h,a1l,a1h,a2l,a2h,a3l,a3h;
        up2(ac0,a0l,a0h); up2(ac1,a1l,a1h); up2(ac2,a2l,a2h); up2(ac3,a3l,a3h);
        *(float4*)(z0p + c4 * 4) = make_float4(a0l, a1l, a2l, a3l);
        *(float4*)(z1p + c4 * 4) = make_float4(a0h, a1h, a2h, a3h);
    }
}

// =====================================================================
// Outer LSTM + dense head: one warp per batch row. Recurrent weights live
// in REGISTERS (48 packed u64 per lane). Gate cols packed f32x2:
// per step = 24 shfl + 48 ffma2 + slim activations. Zero LDS in loop.
// =====================================================================
__global__ void __launch_bounds__(32) outer_kernel(
    const int*   __restrict__ lengths,
    const float* __restrict__ Uo,
    const float* __restrict__ Wd,
    const float* __restrict__ bd,
    float*       __restrict__ out)
{
    const int l  = threadIdx.x;
    const int la = (l < 24) ? l : 0;       // clamped lane (lanes 24..31 idle-safe)
    const int b  = blockIdx.x;

    // register-resident recurrent weights: lane la's 4 gate columns per k
    u64 w_if[24], w_go[24];
    #pragma unroll
    for (int k = 0; k < 24; k++){
        const float* row = Uo + k * 96;
        w_if[k] = pk2(__ldg(row + la),      __ldg(row + 24 + la));
        w_go[k] = pk2(__ldg(row + 48 + la), __ldg(row + 72 + la));
    }

    const int len = lengths[b];            // in [1, T]
    const float* zr = g_zx + (size_t)b * Tn * 96;

    float h = 0.f, c = 0.f;
    u64 znA = pk2(zr[la], zr[24 + la]);
    u64 znB = pk2(zr[48 + la], zr[72 + la]);

    for (int t = 0; t < len; t++){
        u64 zA = znA, zB = znB;
        if (t + 1 < len){
            const float* zq = zr + (size_t)(t + 1) * 96;
            znA = pk2(zq[la], zq[24 + la]);
            znB = pk2(zq[48 + la], zq[72 + la]);
        }
        #pragma unroll
        for (int k = 0; k < 24; k++){
            float hk = __shfl_sync(0xffffffffu, h, k);
            u64 h2 = pk2(hk, hk);
            zA = ffma2(h2, w_if[k], zA);
            zB = ffma2(h2, w_go[k], zB);
        }
        float zi, zf, zg, zo;
        up2(zA, zi, zf);
        up2(zB, zg, zo);
        float fi = sigf(zi), ff = sigf(zf), gg = tanh_f(zg), oo = sigf(zo);
        c = ff * c + fi * gg;
        h = oo * tanh_f(c);
        // lanes >= 24 compute finite garbage, never read (shfl uses k < 24)
    }

    // dense sigmoid head
    float p = (l < 24) ? h * __ldg(Wd + la) : 0.f;
    #pragma unroll
    for (int off = 16; off; off >>= 1) p += __shfl_xor_sync(0xffffffffu, p, off);
    if (l == 0) out[b] = sigf(p + bd[0]);
}

extern "C" void kernel_launch(void* const* d_in, const int* in_sizes, int n_in,
                              void* d_out, int out_size)
{
    const float* x       = (const float*)d_in[0];
    const int*   lengths = (const int*)  d_in[1];
    const float* Wi      = (const float*)d_in[2];
    const float* Ui      = (const float*)d_in[3];
    const float* bi      = (const float*)d_in[4];
    const float* Wo      = (const float*)d_in[5];
    const float* Uo      = (const float*)d_in[6];
    const float* bo      = (const float*)d_in[7];
    const float* Wd      = (const float*)d_in[8];
    const float* bd      = (const float*)d_in[9];
    float* out = (float*)d_out;

    // smem: wuf 32768 + wif 1024 + bif 1024 + xsm 5120 + hsm 16384 = 56320
    const int smem_bytes = 56320;
    cudaFuncSetAttribute(inner_kernel,
                         cudaFuncAttributeMaxDynamicSharedMemorySize, smem_bytes);

    inner_kernel<<<1024, 256, smem_bytes>>>(x, Wi, Ui, bi, Wo, bo);
    outer_kernel<<<256, 32>>>(lengths, Uo, Wd, bd, out);
}